// round 4
// baseline (speedup 1.0000x reference)
#include <cuda_runtime.h>
#include <cuda_bf16.h>
#include <math.h>

#define NNODES 100000
#define NEDGES 1600000
#define DIN 128
#define DHID 128
#define DOUT 64
#define BN_EPS 1e-5f

// buffer selectors
#define SEL_ARG 0
#define SEL_AGG 1
#define SEL_PRE 2
#define SEL_H1  3

// ---------------- scratch (static device globals; no allocation) -------------
__device__ __align__(16) float g_agg[NNODES * DHID];   // propagate output
__device__ __align__(16) float g_pre[NNODES * DHID];   // pre-BN GEMM output
__device__ __align__(16) float g_h1 [NNODES * DHID];   // post-BN layer-1 acts
__device__ int   g_rowptr[NNODES + 1];
__device__ int   g_cursor[NNODES];
__device__ int   g_srcs[NEDGES];
__device__ __align__(16) float g_wts [NEDGES];
__device__ float g_stats[2 * DHID];
__device__ __align__(16) float g_scale[DHID];
__device__ __align__(16) float g_shift[DHID];
__device__ __align__(16) float g_Wt[DHID * DHID];
__device__ int   g_is64;   // 1 if edge_index is int64, 0 if int32

__device__ __forceinline__ const float* sel_cbuf(int sel, const float* arg) {
    switch (sel) {
        case SEL_AGG: return g_agg;
        case SEL_PRE: return g_pre;
        case SEL_H1:  return g_h1;
        default:      return arg;
    }
}
__device__ __forceinline__ float* sel_mbuf(int sel, float* arg) {
    switch (sel) {
        case SEL_AGG: return g_agg;
        case SEL_PRE: return g_pre;
        case SEL_H1:  return g_h1;
        default:      return arg;
    }
}

// edge index fetch honoring runtime dtype flag. ei32 = int32 view of buffer.
//   int32 layout: [src0..srcE-1, dst0..dstE-1]
//   int64 layout (little-endian words): [src0,0, src1,0, ..., dst0,0, ...]
__device__ __forceinline__ int fetch_src(const int* ei32, int e, int is64) {
    return is64 ? ei32[2 * e] : ei32[e];
}
__device__ __forceinline__ int fetch_dst(const int* ei32, int e, int is64) {
    return is64 ? ei32[2 * (NEDGES + e)] : ei32[NEDGES + e];
}

// ---------------- dtype detection --------------------------------------------
// Sample 4096 odd int32 words from the first 8192 words (in-bounds for both
// dtypes). If every one is zero, data is int64 (high words of values < 2^31).
__global__ void detect_dtype_kernel(const int* __restrict__ ei32) {
    __shared__ int s_nonzero;
    if (threadIdx.x == 0) s_nonzero = 0;
    __syncthreads();
    for (int k = threadIdx.x; k < 4096; k += blockDim.x) {
        if (ei32[2 * k + 1] != 0) atomicOr(&s_nonzero, 1);
    }
    __syncthreads();
    if (threadIdx.x == 0) g_is64 = s_nonzero ? 0 : 1;
}

// ---------------- small utility kernels --------------------------------------
__global__ void zero_cursor_kernel() {
    int i = blockIdx.x * blockDim.x + threadIdx.x;
    if (i < NNODES) g_cursor[i] = 0;
}
__global__ void zero_stats_kernel() {
    int i = threadIdx.x;
    if (i < 2 * DHID) g_stats[i] = 0.0f;
}

// ---------------- CSR build ---------------------------------------------------
__global__ void hist_kernel(const int* __restrict__ ei32) {
    int e = blockIdx.x * blockDim.x + threadIdx.x;
    if (e < NEDGES) {
        int d = fetch_dst(ei32, e, g_is64);
        atomicAdd(&g_cursor[d], 1);
    }
}

// single-block chunked exclusive scan over g_cursor -> g_rowptr (+reset cursor)
__global__ void scan_kernel() {
    __shared__ int warp_sums[32];
    __shared__ int s_carry;
    int tid = threadIdx.x, lane = tid & 31, wid = tid >> 5;
    if (tid == 0) s_carry = 0;
    __syncthreads();
    for (int base = 0; base < NNODES; base += 1024) {
        int i = base + tid;
        int v = (i < NNODES) ? g_cursor[i] : 0;
        int x = v;
        #pragma unroll
        for (int d = 1; d < 32; d <<= 1) {
            int y = __shfl_up_sync(0xFFFFFFFFu, x, d);
            if (lane >= d) x += y;
        }
        if (lane == 31) warp_sums[wid] = x;
        __syncthreads();
        if (wid == 0) {
            int ws = warp_sums[lane];
            #pragma unroll
            for (int d = 1; d < 32; d <<= 1) {
                int y = __shfl_up_sync(0xFFFFFFFFu, ws, d);
                if (lane >= d) ws += y;
            }
            warp_sums[lane] = ws;
        }
        __syncthreads();
        int incl = x + (wid > 0 ? warp_sums[wid - 1] : 0);
        int excl = incl - v + s_carry;
        if (i < NNODES) { g_rowptr[i] = excl; g_cursor[i] = excl; }
        int block_total = warp_sums[31];
        __syncthreads();
        if (tid == 0) s_carry += block_total;
        __syncthreads();
    }
    if (threadIdx.x == 0) g_rowptr[NNODES] = s_carry;
}

__global__ void scatter_kernel(const int* __restrict__ ei32,
                               const float* __restrict__ ew) {
    int e = blockIdx.x * blockDim.x + threadIdx.x;
    if (e < NEDGES) {
        int is64 = g_is64;
        int s = fetch_src(ei32, e, is64);
        int d = fetch_dst(ei32, e, is64);
        float w = ew[e];
        int pos = atomicAdd(&g_cursor[d], 1);
        g_srcs[pos] = s;
        g_wts [pos] = w;
    }
}

// ---------------- propagate: warp-per-node CSR gather-reduce -> g_agg ---------
__global__ void propagate_kernel(int hsel, const float* __restrict__ harg) {
    const float* __restrict__ h = sel_cbuf(hsel, harg);
    int warp = (blockIdx.x * blockDim.x + threadIdx.x) >> 5;
    int lane = threadIdx.x & 31;
    if (warp >= NNODES) return;
    int beg = g_rowptr[warp];
    int end = g_rowptr[warp + 1];
    float4 acc = make_float4(0.f, 0.f, 0.f, 0.f);
    for (int e = beg; e < end; e++) {
        int   s = g_srcs[e];
        float w = g_wts[e];
        const float4* vp = (const float4*)(h + (size_t)s * DHID) + lane;
        float4 v = *vp;
        acc.x += w * v.x; acc.y += w * v.y;
        acc.z += w * v.z; acc.w += w * v.w;
    }
    ((float4*)(g_agg + (size_t)warp * DHID))[lane] = acc;
}

// ---------------- weight transpose: W[NC][128] -> g_Wt[128][NC] ---------------
__global__ void transpose_w_kernel(const float* __restrict__ W, int nc) {
    int idx = blockIdx.x * blockDim.x + threadIdx.x;
    if (idx < nc * DHID) {
        int o = idx / DHID, k = idx % DHID;
        g_Wt[k * nc + o] = W[idx];
    }
}

// ---------------- register-tiled fp32 GEMM: C[N,NC] = A[N,128] @ g_Wt + bias --
template <int NC, bool RELU>
__global__ void gemm_bias_kernel(int asel, const float* __restrict__ Aarg,
                                 const float* __restrict__ bias,
                                 int csel, float* __restrict__ Carg) {
    const float* __restrict__ A = sel_cbuf(asel, Aarg);
    float* __restrict__ C = sel_mbuf(csel, Carg);
    constexpr int K = 128, BK = 32, BM = 64;
    constexpr int TCOLS = NC / 4;
    constexpr int TROWS = 256 / TCOLS;
    constexpr int TM = BM / TROWS;
    __shared__ float As[BM][BK];
    __shared__ float Ws[BK][NC];

    int tid  = threadIdx.x;
    int trow = tid / TCOLS, tcol = tid % TCOLS;
    int row0 = blockIdx.x * BM;

    float acc[TM][4];
    #pragma unroll
    for (int m = 0; m < TM; m++) { acc[m][0]=acc[m][1]=acc[m][2]=acc[m][3]=0.f; }

    for (int k0 = 0; k0 < K; k0 += BK) {
        #pragma unroll
        for (int i = 0; i < (BM * BK / 4) / 256; i++) {
            int slot = tid + i * 256;
            int r = slot / (BK / 4), c4 = slot % (BK / 4);
            int gr = row0 + r;
            float4 v = (gr < NNODES)
                ? *(const float4*)(A + (size_t)gr * K + k0 + c4 * 4)
                : make_float4(0.f, 0.f, 0.f, 0.f);
            *(float4*)&As[r][c4 * 4] = v;
        }
        #pragma unroll
        for (int i = 0; i < (BK * NC / 4) / 256; i++) {
            int slot = tid + i * 256;
            int r = slot / (NC / 4), c4 = slot % (NC / 4);
            *(float4*)&Ws[r][c4 * 4] =
                *(const float4*)(g_Wt + (size_t)(k0 + r) * NC + c4 * 4);
        }
        __syncthreads();
        #pragma unroll
        for (int kk = 0; kk < BK; kk++) {
            float4 w = *(float4*)&Ws[kk][tcol * 4];
            #pragma unroll
            for (int m = 0; m < TM; m++) {
                float a = As[trow * TM + m][kk];
                acc[m][0] += a * w.x; acc[m][1] += a * w.y;
                acc[m][2] += a * w.z; acc[m][3] += a * w.w;
            }
        }
        __syncthreads();
    }

    float4 b = *(const float4*)(bias + tcol * 4);
    #pragma unroll
    for (int m = 0; m < TM; m++) {
        int gr = row0 + trow * TM + m;
        if (gr < NNODES) {
            float4 o;
            o.x = acc[m][0] + b.x; o.y = acc[m][1] + b.y;
            o.z = acc[m][2] + b.z; o.w = acc[m][3] + b.w;
            if (RELU) {
                o.x = fmaxf(o.x, 0.f); o.y = fmaxf(o.y, 0.f);
                o.z = fmaxf(o.z, 0.f); o.w = fmaxf(o.w, 0.f);
            }
            *(float4*)(C + (size_t)gr * NC + tcol * 4) = o;
        }
    }
}

// ---------------- BatchNorm (stats over g_pre) --------------------------------
__global__ void bn_stats_kernel() {
    int c = threadIdx.x;                  // 128 threads, one per column
    float s = 0.f, sq = 0.f;
    for (int r = blockIdx.x; r < NNODES; r += gridDim.x) {
        float v = g_pre[(size_t)r * DHID + c];
        s += v; sq += v * v;
    }
    atomicAdd(&g_stats[c], s);
    atomicAdd(&g_stats[DHID + c], sq);
}

__global__ void bn_finalize_kernel(const float* __restrict__ g,
                                   const float* __restrict__ be) {
    int c = threadIdx.x;
    float m = g_stats[c] / (float)NNODES;
    float v = g_stats[DHID + c] / (float)NNODES - m * m;
    float sc = g[c] * rsqrtf(v + BN_EPS);
    g_scale[c] = sc;
    g_shift[c] = be[c] - m * sc;
}

// reads g_pre, writes selected output
__global__ void bn_apply_relu_kernel(int osel, float* __restrict__ oarg) {
    float* __restrict__ out = sel_mbuf(osel, oarg);
    int i = blockIdx.x * blockDim.x + threadIdx.x;   // float4 index
    if (i >= NNODES * DHID / 4) return;
    int c4 = (i % (DHID / 4)) * 4;
    float4 v  = *(const float4*)(g_pre + (size_t)i * 4);
    float4 sc = *(const float4*)(g_scale + c4);
    float4 sh = *(const float4*)(g_shift + c4);
    float4 o;
    o.x = fmaxf(v.x * sc.x + sh.x, 0.f);
    o.y = fmaxf(v.y * sc.y + sh.y, 0.f);
    o.z = fmaxf(v.z * sc.z + sh.z, 0.f);
    o.w = fmaxf(v.w * sc.w + sh.w, 0.f);
    *(float4*)(out + (size_t)i * 4) = o;
}

// ---------------- launch ------------------------------------------------------
extern "C" void kernel_launch(void* const* d_in, const int* in_sizes, int n_in,
                              void* d_out, int out_size) {
    const float* x    = (const float*)d_in[0];
    const int*   ei32 = (const int*)d_in[1];     // int32 OR int64 (detected)
    const float* ew   = (const float*)d_in[2];
    const float* W1   = (const float*)d_in[3];
    const float* b1   = (const float*)d_in[4];
    const float* W2   = (const float*)d_in[5];
    const float* b2   = (const float*)d_in[6];
    const float* W3   = (const float*)d_in[7];
    const float* b3   = (const float*)d_in[8];
    const float* g1   = (const float*)d_in[9];
    const float* be1  = (const float*)d_in[10];
    const float* g2   = (const float*)d_in[11];
    const float* be2  = (const float*)d_in[12];
    const float* pW1  = (const float*)d_in[13];
    const float* pb1  = (const float*)d_in[14];
    const float* pW2  = (const float*)d_in[15];
    const float* pb2  = (const float*)d_in[16];

    float* out_logits = (float*)d_out;                              // [N,64]
    float* out_h      = out_logits + (size_t)NNODES * DOUT;         // [N,128]
    float* out_z      = out_h      + (size_t)NNODES * DHID;         // [N,128]

    const int EB = (NEDGES + 255) / 256;
    const int PB = (NNODES * 32 + 255) / 256;     // warp per node
    const int GB = (NNODES + 63) / 64;
    const int AB = (NNODES * DHID / 4 + 255) / 256;

    // --- dtype detect + CSR build ---
    detect_dtype_kernel<<<1, 1024>>>(ei32);
    zero_cursor_kernel<<<(NNODES + 255) / 256, 256>>>();
    hist_kernel<<<EB, 256>>>(ei32);
    scan_kernel<<<1, 1024>>>();
    scatter_kernel<<<EB, 256>>>(ei32, ew);

    // --- layer 1: propagate(x) @ W1.T + b1 -> bn -> relu -> g_h1 ---
    propagate_kernel<<<PB, 256>>>(SEL_ARG, x);                     // -> g_agg
    transpose_w_kernel<<<(DHID * DHID + 255) / 256, 256>>>(W1, DHID);
    gemm_bias_kernel<DHID, false><<<GB, 256>>>(SEL_AGG, nullptr, b1,
                                               SEL_PRE, nullptr);
    zero_stats_kernel<<<1, 256>>>();
    bn_stats_kernel<<<256, DHID>>>();
    bn_finalize_kernel<<<1, DHID>>>(g1, be1);
    bn_apply_relu_kernel<<<AB, 256>>>(SEL_H1, nullptr);            // g_pre -> g_h1

    // --- layer 2: propagate(g_h1) @ W2.T + b2 -> bn -> relu -> out_h ---
    propagate_kernel<<<PB, 256>>>(SEL_H1, nullptr);                // -> g_agg
    transpose_w_kernel<<<(DHID * DHID + 255) / 256, 256>>>(W2, DHID);
    gemm_bias_kernel<DHID, false><<<GB, 256>>>(SEL_AGG, nullptr, b2,
                                               SEL_PRE, nullptr);
    zero_stats_kernel<<<1, 256>>>();
    bn_stats_kernel<<<256, DHID>>>();
    bn_finalize_kernel<<<1, DHID>>>(g2, be2);
    bn_apply_relu_kernel<<<AB, 256>>>(SEL_ARG, out_h);             // g_pre -> out_h

    // --- logits: propagate(out_h) @ W3.T + b3 -> out_logits ---
    propagate_kernel<<<PB, 256>>>(SEL_ARG, out_h);                 // -> g_agg
    transpose_w_kernel<<<(DOUT * DHID + 255) / 256, 256>>>(W3, DOUT);
    gemm_bias_kernel<DOUT, false><<<GB, 256>>>(SEL_AGG, nullptr, b3,
                                               SEL_ARG, out_logits);

    // --- proj head: z = relu(out_h @ pW1.T + pb1) @ pW2.T + pb2 -> out_z ---
    transpose_w_kernel<<<(DHID * DHID + 255) / 256, 256>>>(pW1, DHID);
    gemm_bias_kernel<DHID, true><<<GB, 256>>>(SEL_ARG, out_h, pb1,
                                              SEL_PRE, nullptr);
    transpose_w_kernel<<<(DHID * DHID + 255) / 256, 256>>>(pW2, DHID);
    gemm_bias_kernel<DHID, false><<<GB, 256>>>(SEL_PRE, nullptr, pb2,
                                               SEL_ARG, out_z);
}